// round 11
// baseline (speedup 1.0000x reference)
#include <cuda_runtime.h>

// R11: instruction-count attack. T=512/GRID=128 (halve warps per SMSP, 1 wave),
// u8 per-(subject,warp) counters in a 16-byte row per subject:
//  - zeroing: 2 int4 stores/thread (was 32 scalar)
//  - the 32-iteration per-subject prefix pass is DELETED: each thread computes
//    its own cross-warp exclusive base via 1 LDS.128 + byte-masked dp4a;
//    block totals via 2x (LDS.128 + dp4a).
// ~60 instr/thread in phase A vs ~400 before. Tail (4 loss blocks): totals,
// exact reference enumeration (pos/neg split), lazy per-pair slot resolution
// over 128 per-block counts, warp-per-pair loss, deterministic combine.

#define NSUBJ 1024
#define T 512
#define NWARP 16          // warps per block
#define MAXGRID 128
#define MAXP 50
#define CAP 51
#define NLOSS 4

__device__ volatile unsigned g_flagA[MAXGRID];  // A-phase published
__device__ volatile unsigned g_flagL[NLOSS];    // loss partial published
__device__ float g_part[NLOSS];
__device__ unsigned short g_bcntT[NSUBJ * MAXGRID];        // [subject][block]
__device__ unsigned short g_lidx[MAXGRID * NSUBJ * CAP];   // [block][subject][slot]

// subject_ids may be int64 or (jax x64-off) int32: one broadcast load + vote.
__device__ __forceinline__ bool detect64(const void* p, int lane) {
    long long v = ((const long long*)p)[lane & 15];
    bool ok = (v >= 0 && v < (long long)NSUBJ);
    return __all_sync(0xFFFFFFFFu, ok);
}

// 0x01 in bytes 0..nb-1 (nb clamped to [0,4]) — dp4a byte-select mask.
__device__ __forceinline__ unsigned bmask(int nb) {
    nb = nb < 0 ? 0 : (nb > 4 ? 4 : nb);
    return nb == 4 ? 0x01010101u : (((1u << (8 * nb)) - 1u) & 0x01010101u);
}

// Warp-cooperative: (subject, global slot) -> global element index.
// Lane l owns blocks 4l..4l+3 (contiguous -> order-correct scan).
__device__ __forceinline__ int resolve_idx(int s, int slot, int lane, int G) {
    const ushort4 c4 = *(const ushort4*)(&g_bcntT[s * MAXGRID + 4 * lane]);
    int b0 = 4 * lane;
    int c[4] = {(int)c4.x, (int)c4.y, (int)c4.z, (int)c4.w};
#pragma unroll
    for (int r = 0; r < 4; r++) if (b0 + r >= G) c[r] = 0;
    int lt = c[0] + c[1] + c[2] + c[3];
    int sc = lt;
#pragma unroll
    for (int d = 1; d < 32; d <<= 1) {
        int t = __shfl_up_sync(0xFFFFFFFFu, sc, d);
        if (lane >= d) sc += t;
    }
    int off = sc - lt;                      // exclusive offset of block b0
    int blk = -1, loc = 0;
#pragma unroll
    for (int r = 0; r < 4; r++) {
        if (slot >= off && slot < off + c[r]) { blk = b0 + r; loc = slot - off; }
        off += c[r];
    }
    int idx = 0;
    if (blk >= 0) idx = blk * T + (int)g_lidx[(blk * NSUBJ + s) * CAP + loc];
    unsigned m = __ballot_sync(0xFFFFFFFFu, blk >= 0);
    return __shfl_sync(0xFFFFFFFFu, idx, __ffs(m) - 1);
}

__global__ void __launch_bounds__(T, 1)
fused_contrastive(const void* __restrict__ sids, const float* __restrict__ x,
                  float* __restrict__ out, int B, int D) {
    __shared__ __align__(16) unsigned char wc8[NSUBJ * NWARP];  // [s*16 + w]
    __shared__ int scnt[NSUBJ];
    __shared__ int ii[2 * MAXP], jj[2 * MAXP];      // encoded s*CAP+slot
    __shared__ int npn[2];
    __shared__ float part[NWARP];

    const int tid = threadIdx.x, lane = tid & 31, w = tid >> 5;
    const int b = blockIdx.x, G = gridDim.x;
    const bool is64 = detect64(sids, lane);
    const unsigned epoch = g_flagA[b] + 1u;         // own flag: replay-safe

    const int i = b * T + tid;                      // one element per thread

    // zero wc8: 1024 int4 words / 512 threads = 2 each
    {
        int4* z = (int4*)wc8;
        const int4 z0 = make_int4(0, 0, 0, 0);
        z[tid] = z0;
        z[tid + T] = z0;
    }
    __syncthreads();

    // ---- A1: single sid load; per-(subject,warp) u8 counts ----
    bool valid = i < B;
    long long v = 0;
    if (valid) v = is64 ? ((const long long*)sids)[i] : (long long)((const int*)sids)[i];
    int s = valid ? (int)v : 0;
    int key = valid ? s : (NSUBJ + lane);
    unsigned mask = __match_any_sync(0xFFFFFFFFu, key);
    int rank = __popc(mask & ((1u << lane) - 1u));  // intra-warp order rank
    if (valid && lane == (__ffs(mask) - 1))
        wc8[s * NWARP + w] += (unsigned char)__popc(mask);
    __syncthreads();

    // ---- A2': per-(block,subject) totals -> g_bcntT (2 subjects/thread) ----
#pragma unroll
    for (int r = 0; r < NSUBJ / T; r++) {
        int s2 = tid + r * T;
        const uint4 row = *(const uint4*)(wc8 + s2 * NWARP);
        unsigned tot = __dp4a(row.x, 0x01010101u,
                       __dp4a(row.y, 0x01010101u,
                       __dp4a(row.z, 0x01010101u,
                       __dp4a(row.w, 0x01010101u, 0u))));
        g_bcntT[s2 * MAXGRID + b] = (unsigned short)tot;
    }

    // ---- A3: ordered local scatter; cross-warp base via masked dp4a ----
    if (valid) {
        const uint4 row = *(const uint4*)(wc8 + s * NWARP);
        unsigned base = __dp4a(row.x, bmask(w),
                        __dp4a(row.y, bmask(w - 4),
                        __dp4a(row.z, bmask(w - 8),
                        __dp4a(row.w, bmask(w - 12), 0u))));
        int slot = (int)base + rank;                // block-local ordered slot
        if (slot < CAP)
            g_lidx[(b * NSUBJ + s) * CAP + slot] = (unsigned short)tid;
    }

    // ---- publish (every thread fences its own stores); non-loss blocks exit ----
    __threadfence();
    __syncthreads();
    if (tid == 0) g_flagA[b] = epoch;
    if (b >= NLOSS) return;

    // ---- wait for all blocks (parallel flag poll) ----
    for (int t = tid; t < G; t += T)
        while (g_flagA[t] < epoch) { }
    __syncthreads();
    __threadfence();

    // ---- B: per-subject totals over G blocks ----
    for (int s2 = tid; s2 < NSUBJ; s2 += T) {
        int tot = 0;
#pragma unroll 16
        for (int c = 0; c < G; c++) tot += (int)g_bcntT[s2 * MAXGRID + c];
        scnt[s2] = tot;
    }
    __syncthreads();

    // ---- D1: exact reference pair enumeration (pos: tid 0, neg: tid 32;
    //      independent given scnt). Handles: s*CAP + global_slot. ----
    if (tid == 0) {                                  // positive pairs
        int npos = 0;
        for (int ss = 0; ss < NSUBJ && npos < MAXP; ss++) {
            int cs = scnt[ss];
            if (cs < 2) continue;
            int til = cs < CAP ? cs : CAP;
            for (int a = 0; a < til && npos < MAXP; a++)
                for (int bb = a + 1; bb < til && npos < MAXP; bb++) {
                    ii[npos] = ss * CAP + a;
                    jj[npos] = ss * CAP + bb;
                    npos++;
                }
        }
        npn[0] = npos;
    }
    if (tid == 32) {                                 // negative pairs
        int nneg = 0;
        for (int ss = 0; ss < NSUBJ && nneg < MAXP; ss++) {
            int cs = scnt[ss];
            if (cs == 0) continue;
            int til = cs < CAP ? cs : CAP;
            for (int o = 0; o < NSUBJ; o++) {
                int co = scnt[o];
                if (co == 0) continue;
                if (o == ss) continue;               // python: continue precedes break
                if (nneg >= MAXP) break;
                int tjl = co < CAP ? co : CAP;
                for (int a = 0; a < til && nneg < MAXP; a++)
                    for (int bb = 0; bb < tjl && nneg < MAXP; bb++) {
                        ii[MAXP + nneg] = ss * CAP + a;
                        jj[MAXP + nneg] = o * CAP + bb;
                        nneg++;
                    }
            }
        }
        npn[1] = nneg;
    }
    __syncthreads();

    // ---- D2: warp per pair (p % NLOSS == b); lazy resolve + loss ----
    const int npos = npn[0], nneg = npn[1], n = npos + nneg;
    float acc = 0.0f;
    const int nvec = D / 4;                          // D=384 -> 96 float4
    for (int p = b + NLOSS * w; p < n; p += NLOSS * NWARP) {
        int slot = (p < npos) ? p : (MAXP + (p - npos));
        int hi = ii[slot], hj = jj[slot];
        int ei = resolve_idx(hi / CAP, hi % CAP, lane, G);
        int ej = resolve_idx(hj / CAP, hj % CAP, lane, G);
        const float4* xi = (const float4*)(x + (long long)ei * D);
        const float4* xj = (const float4*)(x + (long long)ej * D);
        float sxx = 0.f, syy = 0.f, sxy = 0.f;
        for (int q = lane; q < nvec; q += 32) {
            float4 a = xi[q];
            float4 bq = xj[q];
            sxx += a.x * a.x + a.y * a.y + a.z * a.z + a.w * a.w;
            syy += bq.x * bq.x + bq.y * bq.y + bq.z * bq.z + bq.w * bq.w;
            sxy += a.x * bq.x + a.y * bq.y + a.z * bq.z + a.w * bq.w;
        }
#pragma unroll
        for (int o = 16; o; o >>= 1) {
            sxx += __shfl_xor_sync(0xFFFFFFFFu, sxx, o);
            syy += __shfl_xor_sync(0xFFFFFFFFu, syy, o);
            sxy += __shfl_xor_sync(0xFFFFFFFFu, sxy, o);
        }
        float ni = fmaxf(sqrtf(sxx), 1e-12f);
        float nj = fmaxf(sqrtf(syy), 1e-12f);
        float sc = (sxy / (ni * nj)) * 2.0f;         // / TEMPERATURE (0.5)
        float xs = (p < npos) ? -sc : sc;
        acc += fmaxf(xs, 0.f) + log1pf(expf(-fabsf(xs)));  // softplus(xs)
    }

    // acc replicated across lanes -> lane 0's copy IS the warp partial
    if (lane == 0) part[w] = acc;
    __syncthreads();
    if (w == 0) {
        float vv = (lane < NWARP) ? part[lane] : 0.0f;
#pragma unroll
        for (int o = 16; o; o >>= 1) vv += __shfl_xor_sync(0xFFFFFFFFu, vv, o);
        if (lane == 0) {
            g_part[b] = vv;
            __threadfence();
            g_flagL[b] = epoch;
        }
    }

    // ---- block 0 combines the NLOSS partials deterministically ----
    if (b == 0) {
        if (tid < NLOSS)
            while (g_flagL[tid] < epoch) { }
        __syncthreads();
        __threadfence();
        if (tid == 0) {
            float tot = 0.0f;
#pragma unroll
            for (int r = 0; r < NLOSS; r++) tot += g_part[r];
            out[0] = tot / (float)n;
        }
    }
}

extern "C" void kernel_launch(void* const* d_in, const int* in_sizes, int n_in,
                              void* d_out, int out_size) {
    const float* x = (const float*)d_in[0];   // identity_tokens [B, D] fp32
    const void* sids = d_in[1];               // subject_ids [B]
    int B = in_sizes[1];
    int D = in_sizes[0] / B;

    int grid = (B + T - 1) / T;               // 128 for B=65536 (<= MAXGRID)
    fused_contrastive<<<grid, T>>>(sids, x, (float*)d_out, B, D);
}

// round 12
// speedup vs baseline: 1.0453x; 1.0453x over previous
#include <cuda_runtime.h>

// R11: instruction-count attack. T=512/GRID=128 (halve warps per SMSP, 1 wave),
// u8 per-(subject,warp) counters in a 16-byte row per subject:
//  - zeroing: 2 int4 stores/thread (was 32 scalar)
//  - the 32-iteration per-subject prefix pass is DELETED: each thread computes
//    its own cross-warp exclusive base via 1 LDS.128 + byte-masked dp4a;
//    block totals via 2x (LDS.128 + dp4a).
// ~60 instr/thread in phase A vs ~400 before. Tail (4 loss blocks): totals,
// exact reference enumeration (pos/neg split), lazy per-pair slot resolution
// over 128 per-block counts, warp-per-pair loss, deterministic combine.

#define NSUBJ 1024
#define T 512
#define NWARP 16          // warps per block
#define MAXGRID 128
#define MAXP 50
#define CAP 51
#define NLOSS 4

__device__ volatile unsigned g_flagA[MAXGRID];  // A-phase published
__device__ volatile unsigned g_flagL[NLOSS];    // loss partial published
__device__ float g_part[NLOSS];
__device__ unsigned short g_bcntT[NSUBJ * MAXGRID];        // [subject][block]
__device__ unsigned short g_lidx[MAXGRID * NSUBJ * CAP];   // [block][subject][slot]

// subject_ids may be int64 or (jax x64-off) int32: one broadcast load + vote.
__device__ __forceinline__ bool detect64(const void* p, int lane) {
    long long v = ((const long long*)p)[lane & 15];
    bool ok = (v >= 0 && v < (long long)NSUBJ);
    return __all_sync(0xFFFFFFFFu, ok);
}

// 0x01 in bytes 0..nb-1 (nb clamped to [0,4]) — dp4a byte-select mask.
__device__ __forceinline__ unsigned bmask(int nb) {
    nb = nb < 0 ? 0 : (nb > 4 ? 4 : nb);
    return nb == 4 ? 0x01010101u : (((1u << (8 * nb)) - 1u) & 0x01010101u);
}

// Warp-cooperative: (subject, global slot) -> global element index.
// Lane l owns blocks 4l..4l+3 (contiguous -> order-correct scan).
__device__ __forceinline__ int resolve_idx(int s, int slot, int lane, int G) {
    const ushort4 c4 = *(const ushort4*)(&g_bcntT[s * MAXGRID + 4 * lane]);
    int b0 = 4 * lane;
    int c[4] = {(int)c4.x, (int)c4.y, (int)c4.z, (int)c4.w};
#pragma unroll
    for (int r = 0; r < 4; r++) if (b0 + r >= G) c[r] = 0;
    int lt = c[0] + c[1] + c[2] + c[3];
    int sc = lt;
#pragma unroll
    for (int d = 1; d < 32; d <<= 1) {
        int t = __shfl_up_sync(0xFFFFFFFFu, sc, d);
        if (lane >= d) sc += t;
    }
    int off = sc - lt;                      // exclusive offset of block b0
    int blk = -1, loc = 0;
#pragma unroll
    for (int r = 0; r < 4; r++) {
        if (slot >= off && slot < off + c[r]) { blk = b0 + r; loc = slot - off; }
        off += c[r];
    }
    int idx = 0;
    if (blk >= 0) idx = blk * T + (int)g_lidx[(blk * NSUBJ + s) * CAP + loc];
    unsigned m = __ballot_sync(0xFFFFFFFFu, blk >= 0);
    return __shfl_sync(0xFFFFFFFFu, idx, __ffs(m) - 1);
}

__global__ void __launch_bounds__(T, 1)
fused_contrastive(const void* __restrict__ sids, const float* __restrict__ x,
                  float* __restrict__ out, int B, int D) {
    __shared__ __align__(16) unsigned char wc8[NSUBJ * NWARP];  // [s*16 + w]
    __shared__ int scnt[NSUBJ];
    __shared__ int ii[2 * MAXP], jj[2 * MAXP];      // encoded s*CAP+slot
    __shared__ int npn[2];
    __shared__ float part[NWARP];

    const int tid = threadIdx.x, lane = tid & 31, w = tid >> 5;
    const int b = blockIdx.x, G = gridDim.x;
    const bool is64 = detect64(sids, lane);
    const unsigned epoch = g_flagA[b] + 1u;         // own flag: replay-safe

    const int i = b * T + tid;                      // one element per thread

    // zero wc8: 1024 int4 words / 512 threads = 2 each
    {
        int4* z = (int4*)wc8;
        const int4 z0 = make_int4(0, 0, 0, 0);
        z[tid] = z0;
        z[tid + T] = z0;
    }
    __syncthreads();

    // ---- A1: single sid load; per-(subject,warp) u8 counts ----
    bool valid = i < B;
    long long v = 0;
    if (valid) v = is64 ? ((const long long*)sids)[i] : (long long)((const int*)sids)[i];
    int s = valid ? (int)v : 0;
    int key = valid ? s : (NSUBJ + lane);
    unsigned mask = __match_any_sync(0xFFFFFFFFu, key);
    int rank = __popc(mask & ((1u << lane) - 1u));  // intra-warp order rank
    if (valid && lane == (__ffs(mask) - 1))
        wc8[s * NWARP + w] += (unsigned char)__popc(mask);
    __syncthreads();

    // ---- A2': per-(block,subject) totals -> g_bcntT (2 subjects/thread) ----
#pragma unroll
    for (int r = 0; r < NSUBJ / T; r++) {
        int s2 = tid + r * T;
        const uint4 row = *(const uint4*)(wc8 + s2 * NWARP);
        unsigned tot = __dp4a(row.x, 0x01010101u,
                       __dp4a(row.y, 0x01010101u,
                       __dp4a(row.z, 0x01010101u,
                       __dp4a(row.w, 0x01010101u, 0u))));
        g_bcntT[s2 * MAXGRID + b] = (unsigned short)tot;
    }

    // ---- A3: ordered local scatter; cross-warp base via masked dp4a ----
    if (valid) {
        const uint4 row = *(const uint4*)(wc8 + s * NWARP);
        unsigned base = __dp4a(row.x, bmask(w),
                        __dp4a(row.y, bmask(w - 4),
                        __dp4a(row.z, bmask(w - 8),
                        __dp4a(row.w, bmask(w - 12), 0u))));
        int slot = (int)base + rank;                // block-local ordered slot
        if (slot < CAP)
            g_lidx[(b * NSUBJ + s) * CAP + slot] = (unsigned short)tid;
    }

    // ---- publish (every thread fences its own stores); non-loss blocks exit ----
    __threadfence();
    __syncthreads();
    if (tid == 0) g_flagA[b] = epoch;
    if (b >= NLOSS) return;

    // ---- wait for all blocks (parallel flag poll) ----
    for (int t = tid; t < G; t += T)
        while (g_flagA[t] < epoch) { }
    __syncthreads();
    __threadfence();

    // ---- B: per-subject totals over G blocks ----
    for (int s2 = tid; s2 < NSUBJ; s2 += T) {
        int tot = 0;
#pragma unroll 16
        for (int c = 0; c < G; c++) tot += (int)g_bcntT[s2 * MAXGRID + c];
        scnt[s2] = tot;
    }
    __syncthreads();

    // ---- D1: exact reference pair enumeration (pos: tid 0, neg: tid 32;
    //      independent given scnt). Handles: s*CAP + global_slot. ----
    if (tid == 0) {                                  // positive pairs
        int npos = 0;
        for (int ss = 0; ss < NSUBJ && npos < MAXP; ss++) {
            int cs = scnt[ss];
            if (cs < 2) continue;
            int til = cs < CAP ? cs : CAP;
            for (int a = 0; a < til && npos < MAXP; a++)
                for (int bb = a + 1; bb < til && npos < MAXP; bb++) {
                    ii[npos] = ss * CAP + a;
                    jj[npos] = ss * CAP + bb;
                    npos++;
                }
        }
        npn[0] = npos;
    }
    if (tid == 32) {                                 // negative pairs
        int nneg = 0;
        for (int ss = 0; ss < NSUBJ && nneg < MAXP; ss++) {
            int cs = scnt[ss];
            if (cs == 0) continue;
            int til = cs < CAP ? cs : CAP;
            for (int o = 0; o < NSUBJ; o++) {
                int co = scnt[o];
                if (co == 0) continue;
                if (o == ss) continue;               // python: continue precedes break
                if (nneg >= MAXP) break;
                int tjl = co < CAP ? co : CAP;
                for (int a = 0; a < til && nneg < MAXP; a++)
                    for (int bb = 0; bb < tjl && nneg < MAXP; bb++) {
                        ii[MAXP + nneg] = ss * CAP + a;
                        jj[MAXP + nneg] = o * CAP + bb;
                        nneg++;
                    }
            }
        }
        npn[1] = nneg;
    }
    __syncthreads();

    // ---- D2: warp per pair (p % NLOSS == b); lazy resolve + loss ----
    const int npos = npn[0], nneg = npn[1], n = npos + nneg;
    float acc = 0.0f;
    const int nvec = D / 4;                          // D=384 -> 96 float4
    for (int p = b + NLOSS * w; p < n; p += NLOSS * NWARP) {
        int slot = (p < npos) ? p : (MAXP + (p - npos));
        int hi = ii[slot], hj = jj[slot];
        int ei = resolve_idx(hi / CAP, hi % CAP, lane, G);
        int ej = resolve_idx(hj / CAP, hj % CAP, lane, G);
        const float4* xi = (const float4*)(x + (long long)ei * D);
        const float4* xj = (const float4*)(x + (long long)ej * D);
        float sxx = 0.f, syy = 0.f, sxy = 0.f;
        for (int q = lane; q < nvec; q += 32) {
            float4 a = xi[q];
            float4 bq = xj[q];
            sxx += a.x * a.x + a.y * a.y + a.z * a.z + a.w * a.w;
            syy += bq.x * bq.x + bq.y * bq.y + bq.z * bq.z + bq.w * bq.w;
            sxy += a.x * bq.x + a.y * bq.y + a.z * bq.z + a.w * bq.w;
        }
#pragma unroll
        for (int o = 16; o; o >>= 1) {
            sxx += __shfl_xor_sync(0xFFFFFFFFu, sxx, o);
            syy += __shfl_xor_sync(0xFFFFFFFFu, syy, o);
            sxy += __shfl_xor_sync(0xFFFFFFFFu, sxy, o);
        }
        float ni = fmaxf(sqrtf(sxx), 1e-12f);
        float nj = fmaxf(sqrtf(syy), 1e-12f);
        float sc = (sxy / (ni * nj)) * 2.0f;         // / TEMPERATURE (0.5)
        float xs = (p < npos) ? -sc : sc;
        acc += fmaxf(xs, 0.f) + log1pf(expf(-fabsf(xs)));  // softplus(xs)
    }

    // acc replicated across lanes -> lane 0's copy IS the warp partial
    if (lane == 0) part[w] = acc;
    __syncthreads();
    if (w == 0) {
        float vv = (lane < NWARP) ? part[lane] : 0.0f;
#pragma unroll
        for (int o = 16; o; o >>= 1) vv += __shfl_xor_sync(0xFFFFFFFFu, vv, o);
        if (lane == 0) {
            g_part[b] = vv;
            __threadfence();
            g_flagL[b] = epoch;
        }
    }

    // ---- block 0 combines the NLOSS partials deterministically ----
    if (b == 0) {
        if (tid < NLOSS)
            while (g_flagL[tid] < epoch) { }
        __syncthreads();
        __threadfence();
        if (tid == 0) {
            float tot = 0.0f;
#pragma unroll
            for (int r = 0; r < NLOSS; r++) tot += g_part[r];
            out[0] = tot / (float)n;
        }
    }
}

extern "C" void kernel_launch(void* const* d_in, const int* in_sizes, int n_in,
                              void* d_out, int out_size) {
    const float* x = (const float*)d_in[0];   // identity_tokens [B, D] fp32
    const void* sids = d_in[1];               // subject_ids [B]
    int B = in_sizes[1];
    int D = in_sizes[0] / B;

    int grid = (B + T - 1) / T;               // 128 for B=65536 (<= MAXGRID)
    fused_contrastive<<<grid, T>>>(sids, x, (float*)d_out, B, D);
}

// round 13
// speedup vs baseline: 3.1050x; 2.9705x over previous
#include <cuda_runtime.h>

// R13 = R10 skeleton (T=1024, GRID=64, tid0-only fences/publish — the config
// that measured 20.4us) + ONLY the u8/dp4a instruction-count reduction:
//  - wc8[subject][32 warps] u8 rows (32B): zero = 2 int4 stores/thread
//  - A2 32-iteration prefix scan DELETED: totals + per-thread cross-warp
//    exclusive base via LDS.128 + dp4a byte masks
//  - one sid load, one __match_any_sync; mask/rank reused across the sync.
// R12's regressions reverted: fence back to tid0-only, grid back to 64.

#define NSUBJ 1024
#define T 1024
#define NWARP 32
#define GRID 64
#define MAXP 50
#define CAP 51
#define NLOSS 4

__device__ volatile unsigned g_flagA[GRID];   // A-phase published
__device__ volatile unsigned g_flagL[NLOSS];  // loss partial published
__device__ float g_part[NLOSS];
__device__ unsigned short g_bcnt16[GRID * NSUBJ];        // [block][subject]
__device__ unsigned short g_lidx[GRID * NSUBJ * CAP];    // [block][subject][slot]

// subject_ids may be int64 or (jax x64-off) int32: one broadcast load + vote.
__device__ __forceinline__ bool detect64(const void* p, int lane) {
    long long v = ((const long long*)p)[lane & 15];
    bool ok = (v >= 0 && v < (long long)NSUBJ);
    return __all_sync(0xFFFFFFFFu, ok);
}

// 0x01 in bytes 0..nb-1 (nb clamped to [0,4]) — dp4a byte-select mask.
__device__ __forceinline__ unsigned bmask(int nb) {
    nb = nb < 0 ? 0 : (nb > 4 ? 4 : nb);
    return nb == 4 ? 0x01010101u : (((1u << (8 * nb)) - 1u) & 0x01010101u);
}

// Warp-cooperative: (subject, global slot) -> global element index.
// R10-verified: lanes hold counts of blocks lane and lane+32; shfl scan.
__device__ __forceinline__ int resolve_idx(int s, int slot, int lane) {
    int u0 = (int)g_bcnt16[lane * NSUBJ + s];
    int u1 = (int)g_bcnt16[(lane + 32) * NSUBJ + s];
    int s0 = u0, s1 = u1;
#pragma unroll
    for (int d = 1; d < 32; d <<= 1) {
        int t0 = __shfl_up_sync(0xFFFFFFFFu, s0, d);
        int t1 = __shfl_up_sync(0xFFFFFFFFu, s1, d);
        if (lane >= d) { s0 += t0; s1 += t1; }
    }
    int tot0 = __shfl_sync(0xFFFFFFFFu, s0, 31);
    int e0 = s0 - u0;
    int e1 = tot0 + s1 - u1;
    int blk = -1, loc = 0;
    if (slot >= e0 && slot < e0 + u0) { blk = lane;      loc = slot - e0; }
    if (slot >= e1 && slot < e1 + u1) { blk = lane + 32; loc = slot - e1; }
    int idx = 0;
    if (blk >= 0)
        idx = blk * T + (int)g_lidx[(blk * NSUBJ + s) * CAP + loc];
    unsigned m = __ballot_sync(0xFFFFFFFFu, blk >= 0);
    return __shfl_sync(0xFFFFFFFFu, idx, __ffs(m) - 1);
}

__global__ void __launch_bounds__(T, 1)
fused_contrastive(const void* __restrict__ sids, const float* __restrict__ x,
                  float* __restrict__ out, int B, int D) {
    __shared__ __align__(16) unsigned char wc8[NSUBJ * NWARP];  // [s*32 + w] u8
    __shared__ int scnt[NSUBJ];
    __shared__ int ii[2 * MAXP], jj[2 * MAXP];      // encoded s*CAP+slot
    __shared__ int npn[2];
    __shared__ float part[NWARP];

    const int tid = threadIdx.x, lane = tid & 31, w = tid >> 5;
    const int b = blockIdx.x;
    const bool is64 = detect64(sids, lane);
    const unsigned epoch = g_flagA[b] + 1u;         // own flag: replay-safe

    const int i = b * T + tid;                      // one element per thread

    // zero wc8: 2048 int4 words / 1024 threads = 2 each
    {
        int4* z = (int4*)wc8;
        const int4 z0 = make_int4(0, 0, 0, 0);
        z[tid] = z0;
        z[tid + T] = z0;
    }
    __syncthreads();

    // ---- A1: single sid load; per-(subject,warp) u8 counts ----
    const bool valid = i < B;
    long long v = 0;
    if (valid) v = is64 ? ((const long long*)sids)[i] : (long long)((const int*)sids)[i];
    const int s = valid ? (int)v : 0;
    const int key = valid ? s : (NSUBJ + lane);
    const unsigned mask = __match_any_sync(0xFFFFFFFFu, key);
    const int rank = __popc(mask & ((1u << lane) - 1u));  // intra-warp order rank
    if (valid && lane == (__ffs(mask) - 1))
        wc8[s * NWARP + w] += (unsigned char)__popc(mask);
    __syncthreads();

    // ---- A2': per-(block,subject) totals -> g_bcnt16 (1 subject/thread) ----
    {
        const uint4 r0 = *(const uint4*)(wc8 + tid * NWARP);
        const uint4 r1 = *(const uint4*)(wc8 + tid * NWARP + 16);
        unsigned tot = __dp4a(r0.x, 0x01010101u, __dp4a(r0.y, 0x01010101u,
                       __dp4a(r0.z, 0x01010101u, __dp4a(r0.w, 0x01010101u,
                       __dp4a(r1.x, 0x01010101u, __dp4a(r1.y, 0x01010101u,
                       __dp4a(r1.z, 0x01010101u, __dp4a(r1.w, 0x01010101u, 0u))))))));
        g_bcnt16[b * NSUBJ + tid] = (unsigned short)tot;   // coalesced
    }

    // ---- A3: ordered local scatter; cross-warp exclusive base via dp4a ----
    if (valid) {
        const uint4 r0 = *(const uint4*)(wc8 + s * NWARP);
        const uint4 r1 = *(const uint4*)(wc8 + s * NWARP + 16);
        unsigned base = __dp4a(r0.x, bmask(w),      __dp4a(r0.y, bmask(w - 4),
                        __dp4a(r0.z, bmask(w - 8),  __dp4a(r0.w, bmask(w - 12),
                        __dp4a(r1.x, bmask(w - 16), __dp4a(r1.y, bmask(w - 20),
                        __dp4a(r1.z, bmask(w - 24), __dp4a(r1.w, bmask(w - 28), 0u))))))));
        int slot = (int)base + rank;                // block-local ordered slot
        if (slot < CAP)
            g_lidx[(b * NSUBJ + s) * CAP + slot] = (unsigned short)tid;
    }
    __syncthreads();

    // ---- publish (tid0-only fence, as verified in R10); non-loss exit ----
    if (tid == 0) {
        __threadfence();
        g_flagA[b] = epoch;
    }
    if (b >= NLOSS) return;

    // ---- wait for all blocks (parallel flag poll) ----
    for (int t = tid; t < GRID; t += T)
        while (g_flagA[t] < epoch) { }
    __syncthreads();
    __threadfence();

    // ---- B: per-subject totals over 64 blocks (thread s sums its column) ----
    {
        int tot = 0;
#pragma unroll 16
        for (int c = 0; c < GRID; c++) tot += (int)g_bcnt16[c * NSUBJ + tid];
        scnt[tid] = tot;
    }
    __syncthreads();

    // ---- D1: exact reference pair enumeration (pos: tid 0, neg: tid 32) ----
    if (tid == 0) {                                  // positive pairs
        int npos = 0;
        for (int ss = 0; ss < NSUBJ && npos < MAXP; ss++) {
            int cs = scnt[ss];
            if (cs < 2) continue;
            int til = cs < CAP ? cs : CAP;
            for (int a = 0; a < til && npos < MAXP; a++)
                for (int bb = a + 1; bb < til && npos < MAXP; bb++) {
                    ii[npos] = ss * CAP + a;
                    jj[npos] = ss * CAP + bb;
                    npos++;
                }
        }
        npn[0] = npos;
    }
    if (tid == 32) {                                 // negative pairs
        int nneg = 0;
        for (int ss = 0; ss < NSUBJ && nneg < MAXP; ss++) {
            int cs = scnt[ss];
            if (cs == 0) continue;
            int til = cs < CAP ? cs : CAP;
            for (int o = 0; o < NSUBJ; o++) {
                int co = scnt[o];
                if (co == 0) continue;
                if (o == ss) continue;               // python: continue precedes break
                if (nneg >= MAXP) break;
                int tjl = co < CAP ? co : CAP;
                for (int a = 0; a < til && nneg < MAXP; a++)
                    for (int bb = 0; bb < tjl && nneg < MAXP; bb++) {
                        ii[MAXP + nneg] = ss * CAP + a;
                        jj[MAXP + nneg] = o * CAP + bb;
                        nneg++;
                    }
            }
        }
        npn[1] = nneg;
    }
    __syncthreads();

    // ---- D2: warp per pair (p % NLOSS == b); lazy resolve + loss ----
    const int npos = npn[0], nneg = npn[1], n = npos + nneg;
    float acc = 0.0f;
    const int nvec = D / 4;                          // D=384 -> 96 float4
    for (int p = b + NLOSS * w; p < n; p += NLOSS * NWARP) {
        int slot = (p < npos) ? p : (MAXP + (p - npos));
        int hi = ii[slot], hj = jj[slot];
        int ei = resolve_idx(hi / CAP, hi % CAP, lane);
        int ej = resolve_idx(hj / CAP, hj % CAP, lane);
        const float4* xi = (const float4*)(x + (long long)ei * D);
        const float4* xj = (const float4*)(x + (long long)ej * D);
        float sxx = 0.f, syy = 0.f, sxy = 0.f;
        for (int q = lane; q < nvec; q += 32) {
            float4 a = xi[q];
            float4 bq = xj[q];
            sxx += a.x * a.x + a.y * a.y + a.z * a.z + a.w * a.w;
            syy += bq.x * bq.x + bq.y * bq.y + bq.z * bq.z + bq.w * bq.w;
            sxy += a.x * bq.x + a.y * bq.y + a.z * bq.z + a.w * bq.w;
        }
#pragma unroll
        for (int o = 16; o; o >>= 1) {
            sxx += __shfl_xor_sync(0xFFFFFFFFu, sxx, o);
            syy += __shfl_xor_sync(0xFFFFFFFFu, syy, o);
            sxy += __shfl_xor_sync(0xFFFFFFFFu, sxy, o);
        }
        float ni = fmaxf(sqrtf(sxx), 1e-12f);
        float nj = fmaxf(sqrtf(syy), 1e-12f);
        float sc = (sxy / (ni * nj)) * 2.0f;         // / TEMPERATURE (0.5)
        float xs = (p < npos) ? -sc : sc;
        acc += fmaxf(xs, 0.f) + log1pf(expf(-fabsf(xs)));  // softplus(xs)
    }

    // acc replicated across lanes -> lane 0's copy IS the warp partial
    if (lane == 0) part[w] = acc;
    __syncthreads();
    if (w == 0) {
        float vv = part[lane];
#pragma unroll
        for (int o = 16; o; o >>= 1) vv += __shfl_xor_sync(0xFFFFFFFFu, vv, o);
        if (lane == 0) {
            g_part[b] = vv;
            __threadfence();
            g_flagL[b] = epoch;
        }
    }

    // ---- block 0 combines the NLOSS partials deterministically ----
    if (b == 0) {
        if (tid < NLOSS)
            while (g_flagL[tid] < epoch) { }
        __syncthreads();
        __threadfence();
        if (tid == 0) {
            float tot = 0.0f;
#pragma unroll
            for (int r = 0; r < NLOSS; r++) tot += g_part[r];
            out[0] = tot / (float)n;
        }
    }
}

extern "C" void kernel_launch(void* const* d_in, const int* in_sizes, int n_in,
                              void* d_out, int out_size) {
    const float* x = (const float*)d_in[0];   // identity_tokens [B, D] fp32
    const void* sids = d_in[1];               // subject_ids [B]
    int B = in_sizes[1];
    int D = in_sizes[0] / B;

    fused_contrastive<<<GRID, T>>>(sids, x, (float*)d_out, B, D);
}

// round 14
// speedup vs baseline: 4.4552x; 1.4349x over previous
#include <cuda_runtime.h>

// R14 = R10 skeleton (verified 20.4us: u32 transposed wc, tid0 publish,
// split enumeration, lazy resolve, deterministic combine) + 3 structural cuts:
//  1. GRID=32, e=2: half the flags, skew, resolve width, B width.
//  2. counts published TRANSPOSED g_bcntT[s][block]: resolve fetch = one
//     coalesced 64B row per warp; B phase = 4x LDG.128 per thread.
//  3. two flags: counts publish after A2 (before scatter) so loss blocks'
//     B + enumeration overlap the other blocks' scatter.

#define NSUBJ 1024
#define T 1024
#define NWARP 32
#define GRID 32
#define E 2
#define ET (E * T)        // 2048 elements per block
#define MAXP 50
#define CAP 51
#define NLOSS 4

#define WCNT_B (NWARP * NSUBJ * 4)       // 131072 (u32, [warp][subject])
#define SMEM_TOTAL (WCNT_B + 4096 /*scnt*/ + 2*MAXP*4*2 + 16 + 128 + 64)

__device__ volatile unsigned g_flagCnt[GRID];   // per-block counts published
__device__ volatile unsigned g_flagScat[GRID];  // scatter published
__device__ volatile unsigned g_flagL[NLOSS];    // loss partial published
__device__ float g_part[NLOSS];
__device__ unsigned short g_bcntT[NSUBJ * GRID];        // [subject][block] (transposed)
__device__ unsigned short g_lidx[GRID * NSUBJ * CAP];   // [block][subject][slot] local idx

// subject_ids may be int64 or (jax x64-off) int32: one broadcast load + vote.
__device__ __forceinline__ bool detect64(const void* p, int lane) {
    long long v = ((const long long*)p)[lane & 15];
    bool ok = (v >= 0 && v < (long long)NSUBJ);
    return __all_sync(0xFFFFFFFFu, ok);
}

__device__ __forceinline__ long long sid_or_neg(const void* p, int i, int B, bool is64) {
    if (i >= B) return -1ll;
    return is64 ? ((const long long*)p)[i] : (long long)((const int*)p)[i];
}

// Warp-cooperative: (subject, global slot) -> global element index.
// One coalesced 64B row load (g_bcntT[s][0..31]), 5-step shfl scan.
__device__ __forceinline__ int resolve_idx(int s, int slot, int lane) {
    int u = (int)g_bcntT[s * GRID + lane];          // coalesced u16 row
    int sc = u;
#pragma unroll
    for (int d = 1; d < 32; d <<= 1) {
        int t = __shfl_up_sync(0xFFFFFFFFu, sc, d);
        if (lane >= d) sc += t;
    }
    int e0 = sc - u;                                // exclusive offset of block `lane`
    bool hit = (slot >= e0) && (slot < e0 + u);
    int idx = 0;
    if (hit)
        idx = lane * ET + (int)g_lidx[(lane * NSUBJ + s) * CAP + (slot - e0)];
    unsigned m = __ballot_sync(0xFFFFFFFFu, hit);
    return __shfl_sync(0xFFFFFFFFu, idx, __ffs(m) - 1);
}

__global__ void __launch_bounds__(T, 1)
fused_contrastive(const void* __restrict__ sids, const float* __restrict__ x,
                  float* __restrict__ out, int B, int D) {
    extern __shared__ unsigned char sm[];
    unsigned* wc = (unsigned*)sm;                   // [warp*NSUBJ + s] u32
    int* scnt = (int*)(sm + WCNT_B);                // [s] totals (loss blocks)
    int* ii   = scnt + NSUBJ;                       // encoded s*CAP+slot
    int* jj   = ii + 2 * MAXP;
    int* npn  = jj + 2 * MAXP;
    float* part = (float*)(npn + 4);                // [32]

    const int tid = threadIdx.x, lane = tid & 31, w = tid >> 5;
    const int b = blockIdx.x;
    const bool is64 = detect64(sids, lane);
    const unsigned epoch = g_flagCnt[b] + 1u;       // own flag: replay-safe

    const int base = b * ET + w * (E * 32);         // warp-contiguous range

    // zero wc (consecutive words per thread: conflict-free)
    for (int k = tid; k < NWARP * NSUBJ; k += T) wc[k] = 0u;
    __syncthreads();

    // ---- A1: per-(subject,warp) counts, E rounds; retain sids in regs ----
    long long vr[E];
#pragma unroll
    for (int k = 0; k < E; k++)
        vr[k] = sid_or_neg(sids, base + k * 32 + lane, B, is64);
#pragma unroll
    for (int k = 0; k < E; k++) {
        bool valid = vr[k] >= 0;
        int s = valid ? (int)vr[k] : 0;
        int key = valid ? s : (NSUBJ + lane);
        unsigned mask = __match_any_sync(0xFFFFFFFFu, key);
        if (valid && lane == (__ffs(mask) - 1))
            wc[w * NSUBJ + s] += __popc(mask);
    }
    __syncthreads();

    // ---- A2: block-local exclusive prefix over warps (conflict-free scan);
    //      publish per-block count TRANSPOSED, then flagCnt ----
    {
        int s = tid;
        int run = 0;
#pragma unroll
        for (int c = 0; c < NWARP; c++) {
            int v = (int)wc[c * NSUBJ + s];
            wc[c * NSUBJ + s] = (unsigned)run;
            run += v;
        }
        g_bcntT[s * GRID + b] = (unsigned short)run;
    }
    __syncthreads();
    if (tid == 0) {
        __threadfence();
        g_flagCnt[b] = epoch;
    }

    // ---- A3: block-LOCAL order-preserving scatter, E rounds ----
#pragma unroll
    for (int k = 0; k < E; k++) {
        int i = base + k * 32 + lane;
        bool valid = vr[k] >= 0;
        int s = valid ? (int)vr[k] : 0;
        int key = valid ? s : (NSUBJ + lane);
        unsigned mask = __match_any_sync(0xFFFFFFFFu, key);
        if (valid) {
            int rank = __popc(mask & ((1u << lane) - 1u));
            int cur = (int)wc[w * NSUBJ + s];       // all lanes read before leader store
            int slot = cur + rank;                  // LOCAL slot
            if (lane == (__ffs(mask) - 1))
                wc[w * NSUBJ + s] = (unsigned)(cur + __popc(mask));
            if (slot < CAP)
                g_lidx[(b * NSUBJ + s) * CAP + slot] = (unsigned short)(i - b * ET);
        }
    }
    __syncthreads();

    // ---- publish scatter; non-loss blocks exit ----
    if (tid == 0) {
        __threadfence();
        g_flagScat[b] = epoch;
    }
    if (b >= NLOSS) return;

    // ---- wait for all COUNTS (overlaps others' scatter) ----
    for (int t = tid; t < GRID; t += T)
        while (g_flagCnt[t] < epoch) { }
    __syncthreads();
    __threadfence();

    // ---- B: per-subject totals; thread s reads its contiguous 64B row ----
    {
        const uint4* row = (const uint4*)(&g_bcntT[tid * GRID]);
        uint4 r0 = row[0], r1 = row[1], r2 = row[2], r3 = row[3];
        unsigned t0 = r0.x + r0.y + r0.z + r0.w + r1.x + r1.y + r1.z + r1.w
                    + r2.x + r2.y + r2.z + r2.w + r3.x + r3.y + r3.z + r3.w;
        scnt[tid] = (int)((t0 & 0xFFFFu) + (t0 >> 16));   // sum of 32 u16
    }
    __syncthreads();

    // ---- D1: exact reference pair enumeration (pos: tid 0, neg: tid 32;
    //      independent given scnt). Handles: s*CAP + global_slot. ----
    if (tid == 0) {                                  // positive pairs
        int npos = 0;
        for (int ss = 0; ss < NSUBJ && npos < MAXP; ss++) {
            int cs = scnt[ss];
            if (cs < 2) continue;
            int til = cs < CAP ? cs : CAP;
            for (int a = 0; a < til && npos < MAXP; a++)
                for (int bb = a + 1; bb < til && npos < MAXP; bb++) {
                    ii[npos] = ss * CAP + a;
                    jj[npos] = ss * CAP + bb;
                    npos++;
                }
        }
        npn[0] = npos;
    }
    if (tid == 32) {                                 // negative pairs
        int nneg = 0;
        for (int ss = 0; ss < NSUBJ && nneg < MAXP; ss++) {
            int cs = scnt[ss];
            if (cs == 0) continue;
            int til = cs < CAP ? cs : CAP;
            for (int o = 0; o < NSUBJ; o++) {
                int co = scnt[o];
                if (co == 0) continue;
                if (o == ss) continue;               // python: continue precedes break
                if (nneg >= MAXP) break;
                int tjl = co < CAP ? co : CAP;
                for (int a = 0; a < til && nneg < MAXP; a++)
                    for (int bb = 0; bb < tjl && nneg < MAXP; bb++) {
                        ii[MAXP + nneg] = ss * CAP + a;
                        jj[MAXP + nneg] = o * CAP + bb;
                        nneg++;
                    }
            }
        }
        npn[1] = nneg;
    }

    // ---- wait for all SCATTERS (g_lidx reads below need them) ----
    for (int t = tid; t < GRID; t += T)
        while (g_flagScat[t] < epoch) { }
    __syncthreads();
    __threadfence();

    // ---- D2: warp per pair (p % NLOSS == b); lazy resolve + loss ----
    const int npos = npn[0], nneg = npn[1], n = npos + nneg;
    float acc = 0.0f;
    const int nvec = D / 4;                          // D=384 -> 96 float4
    for (int p = b + NLOSS * w; p < n; p += NLOSS * NWARP) {
        int slot = (p < npos) ? p : (MAXP + (p - npos));
        int hi = ii[slot], hj = jj[slot];
        int ei = resolve_idx(hi / CAP, hi % CAP, lane);
        int ej = resolve_idx(hj / CAP, hj % CAP, lane);
        const float4* xi = (const float4*)(x + (long long)ei * D);
        const float4* xj = (const float4*)(x + (long long)ej * D);
        float sxx = 0.f, syy = 0.f, sxy = 0.f;
        for (int q = lane; q < nvec; q += 32) {
            float4 a = xi[q];
            float4 bq = xj[q];
            sxx += a.x * a.x + a.y * a.y + a.z * a.z + a.w * a.w;
            syy += bq.x * bq.x + bq.y * bq.y + bq.z * bq.z + bq.w * bq.w;
            sxy += a.x * bq.x + a.y * bq.y + a.z * bq.z + a.w * bq.w;
        }
#pragma unroll
        for (int o = 16; o; o >>= 1) {
            sxx += __shfl_xor_sync(0xFFFFFFFFu, sxx, o);
            syy += __shfl_xor_sync(0xFFFFFFFFu, syy, o);
            sxy += __shfl_xor_sync(0xFFFFFFFFu, sxy, o);
        }
        float ni = fmaxf(sqrtf(sxx), 1e-12f);
        float nj = fmaxf(sqrtf(syy), 1e-12f);
        float sc = (sxy / (ni * nj)) * 2.0f;         // / TEMPERATURE (0.5)
        float xs = (p < npos) ? -sc : sc;
        acc += fmaxf(xs, 0.f) + log1pf(expf(-fabsf(xs)));  // softplus(xs)
    }

    // acc replicated across lanes -> lane 0's copy IS the warp partial
    if (lane == 0) part[w] = acc;
    __syncthreads();
    if (w == 0) {
        float vv = part[lane];
#pragma unroll
        for (int o = 16; o; o >>= 1) vv += __shfl_xor_sync(0xFFFFFFFFu, vv, o);
        if (lane == 0) {
            g_part[b] = vv;
            __threadfence();
            g_flagL[b] = epoch;
        }
    }

    // ---- block 0 combines the NLOSS partials deterministically ----
    if (b == 0) {
        if (tid < NLOSS)
            while (g_flagL[tid] < epoch) { }
        __syncthreads();
        __threadfence();
        if (tid == 0) {
            float tot = 0.0f;
#pragma unroll
            for (int r = 0; r < NLOSS; r++) tot += g_part[r];
            out[0] = tot / (float)n;
        }
    }
}

extern "C" void kernel_launch(void* const* d_in, const int* in_sizes, int n_in,
                              void* d_out, int out_size) {
    const float* x = (const float*)d_in[0];   // identity_tokens [B, D] fp32
    const void* sids = d_in[1];               // subject_ids [B]
    int B = in_sizes[1];
    int D = in_sizes[0] / B;

    cudaFuncSetAttribute(fused_contrastive,
                         cudaFuncAttributeMaxDynamicSharedMemorySize, SMEM_TOTAL);

    fused_contrastive<<<GRID, T, SMEM_TOTAL>>>(sids, x, (float*)d_out, B, D);
}